// round 5
// baseline (speedup 1.0000x reference)
#include <cuda_runtime.h>
#include <math.h>

#define BB 16
#define SEQ 4107
#define NTOK 4096
#define DIMD 768
#define LATD 20
#define NP 10
#define NROWS_X (BB*SEQ)
#define NROWS_L (BB*NTOK)
#define SPLIT 8
#define CHUNK (NTOK/SPLIT)   // 512

typedef unsigned long long ull;

// ---------------- scratch (device globals: no allocation allowed) ----------------
__device__ __align__(16) float g_xlat[NROWS_X*LATD];   // x latents; prompt rows later overwritten with "enhanced"
__device__ __align__(16) float g_llat[NROWS_L*LATD];   // local latents
__device__ float g_qg[BB*NP*LATD];
__device__ float g_ql[BB*NP*LATD];
__device__ float g_pi[BB*NP];
__device__ float g_gw[BB];
__device__ float g_part[BB*2*NP*SPLIT*22];             // per-split softmax partials: m, s, acc[20]

__device__ __forceinline__ float warp_sum(float v) {
#pragma unroll
    for (int o = 16; o; o >>= 1) v += __shfl_xor_sync(0xffffffffu, v, o);
    return v;
}
__device__ __forceinline__ float warp_max(float v) {
#pragma unroll
    for (int o = 16; o; o >>= 1) v = fmaxf(v, __shfl_xor_sync(0xffffffffu, v, o));
    return v;
}
__device__ __forceinline__ ull fma2(ull a, ull b, ull c) {
    ull d;
    asm("fma.rn.f32x2 %0, %1, %2, %3;" : "=l"(d) : "l"(a), "l"(b), "l"(c));
    return d;
}
__device__ __forceinline__ float lo2(ull v) { float2 f = *(float2*)&v; return f.x; }
__device__ __forceinline__ float hi2(ull v) { float2 f = *(float2*)&v; return f.y; }

// ---------------- Kernel 1: latent = quick_gelu(X @ Wd + bd) ----------------
// f32x2 packed along K: x pairs staged as float2 in smem (one LDS.64 per k-pair),
// Wd pre-packed pair-interleaved so one LDS.128 yields two (k0,k1) weight pairs.
// 20 FMA2 per k-pair covers 40 scalar FMAs -> halves FMA-pipe issue time.
#define KC 32
#define KP (KC/2)
#define TILE_ROWS 256
#define ST2 (TILE_ROWS + 1)   // float2 stride per k-pair row

__global__ void __launch_bounds__(256)
latent_kernel(const float* __restrict__ X,
              const float* __restrict__ Wd,
              const float* __restrict__ bd,
              int nRows, int which) {
    extern __shared__ float smem[];
    float*  wds2 = smem;                              // DIMD*LATD floats, pair-interleaved
    float2* xs2  = (float2*)(smem + DIMD*LATD);       // KP * ST2 float2
    float*  dst  = which ? g_llat : g_xlat;

    int tid = threadIdx.x;
    // stage Wd packed: pos = (k/2)*40 + l*2 + (k&1)
    for (int idx = tid; idx < DIMD*LATD; idx += 256) {
        int k = idx / LATD, l = idx % LATD;
        wds2[(k >> 1)*40 + l*2 + (k & 1)] = Wd[idx];
    }

    int rowBase = blockIdx.x * TILE_ROWS;
    int myRow = rowBase + tid;

    ull acc2[LATD];
#pragma unroll
    for (int l = 0; l < LATD; l++) acc2[l] = 0ull;

    for (int kc = 0; kc < DIMD; kc += KC) {
        __syncthreads();
        // cooperative load: 256 rows x KC cols as float4, stored as k-pair float2s
#pragma unroll
        for (int it = 0; it < (TILE_ROWS*KC/4)/256; it++) {
            int i = tid + it*256;
            int r  = i >> 3;          // KC/4 = 8 float4 per row
            int k4 = i & 7;
            float4 v = make_float4(0.f, 0.f, 0.f, 0.f);
            int gr = rowBase + r;
            if (gr < nRows) v = *(const float4*)(X + (size_t)gr*DIMD + kc + k4*4);
            xs2[(k4*2    )*ST2 + r] = make_float2(v.x, v.y);
            xs2[(k4*2 + 1)*ST2 + r] = make_float2(v.z, v.w);
        }
        __syncthreads();
#pragma unroll 4
        for (int kp = 0; kp < KP; kp++) {
            ull xv2 = *(const ull*)&xs2[kp*ST2 + tid];
            const ulonglong2* wr = (const ulonglong2*)(wds2 + ((kc >> 1) + kp)*40);
#pragma unroll
            for (int l4 = 0; l4 < 10; l4++) {
                ulonglong2 wv = wr[l4];
                acc2[2*l4    ] = fma2(xv2, wv.x, acc2[2*l4    ]);
                acc2[2*l4 + 1] = fma2(xv2, wv.y, acc2[2*l4 + 1]);
            }
        }
    }

    if (myRow < nRows) {
        float4 o4[5];
        float* ov = (float*)o4;
#pragma unroll
        for (int l = 0; l < LATD; l++) {
            float z = lo2(acc2[l]) + hi2(acc2[l]) + bd[l];
            ov[l] = z * (1.f / (1.f + __expf(-1.702f * z)));   // quick_gelu
        }
        float4* d4 = (float4*)(dst + (size_t)myRow*LATD);
#pragma unroll
        for (int q = 0; q < 5; q++) d4[q] = o4[q];
    }
}

// ---------------- Kernel 2: per-batch head math (1 warp per batch) ----------------
__global__ void __launch_bounds__(32)
head_kernel(const float* __restrict__ ln_c_g, const float* __restrict__ ln_c_b,
            const float* __restrict__ Wc1,    const float* __restrict__ bc1,
            const float* __restrict__ Wc2,    const float* __restrict__ bc2,
            const float* __restrict__ ln_g_g, const float* __restrict__ ln_g_b,
            const float* __restrict__ Wg,     const float* __restrict__ bg,
            const float* __restrict__ Wgq,    const float* __restrict__ bgq,
            const float* __restrict__ Wlq,    const float* __restrict__ blq) {
    int b = blockIdx.x;
    int lane = threadIdx.x;
    __shared__ float pr[NP*LATD];
    __shared__ float clsln[LATD];
    __shared__ float h[64];

    const float* base = g_xlat + (size_t)b*SEQ*LATD;
    for (int i = lane; i < NP*LATD; i += 32) pr[i] = base[i];

    float c = (lane < LATD) ? base[NP*LATD + lane] : 0.f;      // cls latent
    float mu = warp_sum(c) * (1.f/LATD);
    float d = (lane < LATD) ? (c - mu) : 0.f;
    float var = warp_sum(d*d) * (1.f/LATD);
    float rs = rsqrtf(var + 1e-5f);
    if (lane < LATD) clsln[lane] = d*rs*ln_c_g[lane] + ln_c_b[lane];
    __syncwarp();

    // h = gelu_exact(cls_ln @ Wc1 + bc1)
    for (int j = lane; j < 64; j += 32) {
        float s = bc1[j];
#pragma unroll
        for (int l = 0; l < LATD; l++) s = fmaf(clsln[l], Wc1[l*64 + j], s);
        h[j] = 0.5f*s*(1.f + erff(s*0.70710678118654752f));
    }
    __syncwarp();

    // prompt importance = sigmoid(h @ Wc2 + bc2)
    if (lane < NP) {
        float s = bc2[lane];
#pragma unroll
        for (int j = 0; j < 64; j++) s = fmaf(h[j], Wc2[j*NP + lane], s);
        g_pi[b*NP + lane] = 1.f/(1.f + __expf(-s));
    }

    // global weight = sigmoid(LN_g(cls) @ Wg + bg)
    float g2 = (lane < LATD) ? (d*rs*ln_g_g[lane] + ln_g_b[lane]) * Wg[lane] : 0.f;
    float sg = warp_sum(g2);
    if (lane == 0) g_gw[b] = 1.f/(1.f + __expf(-(sg + bg[0])));

    // q projections
    if (lane < LATD) {
        for (int p = 0; p < NP; p++) {
            float sq = bgq[lane], sl = blq[lane];
#pragma unroll
            for (int l = 0; l < LATD; l++) {
                float pv = pr[p*LATD + l];
                sq = fmaf(pv, Wgq[l*LATD + lane], sq);
                sl = fmaf(pv, Wlq[l*LATD + lane], sl);
            }
            g_qg[(b*NP + p)*LATD + lane] = sq;
            g_ql[(b*NP + p)*LATD + lane] = sl;
        }
    }
}

// ---------------- Kernel 3a: split-softmax attention partials ----------------
// grid = BB*2*SPLIT blocks, 320 threads = 10 warps; warp w = prompt w.
// Token chunk (512 tokens) staged ONCE in smem, shared by all 10 prompts.
__global__ void __launch_bounds__(320, 1)
attn_part_kernel() {
    int blk = blockIdx.x;
    int b = blk / (2*SPLIT);
    int rem = blk % (2*SPLIT);
    int which = rem >> 3;      // /SPLIT
    int sp = rem & (SPLIT-1);
    int tid = threadIdx.x, w = tid >> 5, lane = tid & 31;

    __shared__ __align__(16) float ts[CHUNK*LATD];   // 40 KB
    __shared__ float qs[NP*LATD];

    const float* tok = which
        ? (g_llat + ((size_t)b*NTOK + sp*CHUNK)*LATD)
        : (g_xlat + ((size_t)b*SEQ + NP + 1 + sp*CHUNK)*LATD);
    const float* qsrc = which ? g_ql : g_qg;

    for (int i = tid; i < CHUNK*LATD/4; i += 320)
        ((float4*)ts)[i] = ((const float4*)tok)[i];
    for (int i = tid; i < NP*LATD; i += 320)
        qs[i] = qsrc[(size_t)b*NP*LATD + i];
    __syncthreads();

    const float scale = 0.22360679774997896f;   // LATENT^-0.5
    float q[LATD];
#pragma unroll
    for (int l = 0; l < LATD; l++) q[l] = qs[w*LATD + l];

    // pass A: scores for this lane's 16 tokens + max
    float sc[16];
    float m = -1e30f;
#pragma unroll
    for (int t = 0; t < 16; t++) {
        const float4* t4 = (const float4*)(ts + (t*32 + lane)*LATD);
        float s = 0.f;
#pragma unroll
        for (int l4 = 0; l4 < 5; l4++) {
            float4 tv = t4[l4];
            s = fmaf(tv.x, q[l4*4+0], s);
            s = fmaf(tv.y, q[l4*4+1], s);
            s = fmaf(tv.z, q[l4*4+2], s);
            s = fmaf(tv.w, q[l4*4+3], s);
        }
        sc[t] = s * scale;
        m = fmaxf(m, sc[t]);
    }
    m = warp_max(m);

    // pass B: exp, sum, weighted accumulation
    float sum = 0.f;
    float acc[LATD];
#pragma unroll
    for (int l = 0; l < LATD; l++) acc[l] = 0.f;
#pragma unroll
    for (int t = 0; t < 16; t++) {
        float e = __expf(sc[t] - m);
        sum += e;
        const float4* t4 = (const float4*)(ts + (t*32 + lane)*LATD);
#pragma unroll
        for (int l4 = 0; l4 < 5; l4++) {
            float4 tv = t4[l4];
            acc[l4*4+0] = fmaf(e, tv.x, acc[l4*4+0]);
            acc[l4*4+1] = fmaf(e, tv.y, acc[l4*4+1]);
            acc[l4*4+2] = fmaf(e, tv.z, acc[l4*4+2]);
            acc[l4*4+3] = fmaf(e, tv.w, acc[l4*4+3]);
        }
    }
    sum = warp_sum(sum);
#pragma unroll
    for (int l = 0; l < LATD; l++) acc[l] = warp_sum(acc[l]);

    if (lane == 0) {
        float* dst = g_part + ((((size_t)(b*2 + which)*NP + w)*SPLIT + sp)*22);
        dst[0] = m;
        dst[1] = sum;
#pragma unroll
        for (int l = 0; l < LATD; l++) dst[2 + l] = acc[l];
    }
}

// ---------------- Kernel 3b: combine partials + fuse + enhance ----------------
// grid = BB*NP blocks of 32 threads (one warp per (b,p)).
__global__ void __launch_bounds__(32)
attn_combine_kernel() {
    int b = blockIdx.x / NP, p = blockIdx.x % NP;
    int lane = threadIdx.x;
    float ctxv[2];

#pragma unroll
    for (int which = 0; which < 2; which++) {
        const float* base = g_part + (((size_t)(b*2 + which)*NP + p)*SPLIT)*22;
        float mloc = (lane < SPLIT) ? base[lane*22] : -1e30f;
        float M = warp_max(mloc);
        float wfac = (lane < SPLIT) ? __expf(base[lane*22] - M) : 0.f;
        float S = warp_sum((lane < SPLIT) ? wfac * base[lane*22 + 1] : 0.f);
        float a = 0.f;
#pragma unroll
        for (int s = 0; s < SPLIT; s++) {
            float ws = __shfl_sync(0xffffffffu, wfac, s);
            if (lane < LATD) a = fmaf(base[s*22 + 2 + lane], ws, a);
        }
        ctxv[which] = a / S;
    }
    if (lane < LATD) {
        float g = g_gw[b], im = g_pi[b*NP + p];
        g_xlat[((size_t)b*SEQ + p)*LATD + lane] = im * (g*ctxv[0] + (1.f - g)*ctxv[1]);
    }
}

// ---------------- Kernel 4: out = combined @ Wu + bu (f32x2 over l-pairs) ----------------
// Wu packed as (l, l+1) pairs in 60 regs/thread; latent row read as LDS.128 broadcast
// giving packed l-pairs for free. 30 FMA2 per row replaces 60 FFMA.
__global__ void __launch_bounds__(256)
out_kernel(const float* __restrict__ Wu,
           const float* __restrict__ bu,
           float* __restrict__ out) {
    __shared__ __align__(16) float ls[32*LATD];
    int tid = threadIdx.x;

    ull wu2[10][3];
#pragma unroll
    for (int i = 0; i < 10; i++)
#pragma unroll
        for (int c = 0; c < 3; c++) {
            float2 pr = make_float2(Wu[(2*i    )*DIMD + tid + c*256],
                                    Wu[(2*i + 1)*DIMD + tid + c*256]);
            wu2[i][c] = *(ull*)&pr;
        }
    float bu3[3];
#pragma unroll
    for (int c = 0; c < 3; c++) bu3[c] = bu[tid + c*256];

    int nTiles = (NROWS_X + 31) / 32;
    for (int t = blockIdx.x; t < nTiles; t += gridDim.x) {
        int rowBase = t * 32;
        __syncthreads();
#pragma unroll
        for (int it = 0; it < 3; it++) {
            int i = tid + it*256;
            if (i < 32*LATD && (size_t)rowBase*LATD + i < (size_t)NROWS_X*LATD)
                ls[i] = g_xlat[(size_t)rowBase*LATD + i];
        }
        __syncthreads();
        int rmax = min(32, NROWS_X - rowBase);
        for (int r = 0; r < rmax; r++) {
            ull a0 = 0ull, a1 = 0ull, a2 = 0ull;
            const ulonglong2* lr = (const ulonglong2*)(ls + r*LATD);   // 5 x LDS.128 broadcast
#pragma unroll
            for (int i2 = 0; i2 < 5; i2++) {
                ulonglong2 lv = lr[i2];
                a0 = fma2(lv.x, wu2[2*i2][0], a0);
                a1 = fma2(lv.x, wu2[2*i2][1], a1);
                a2 = fma2(lv.x, wu2[2*i2][2], a2);
                a0 = fma2(lv.y, wu2[2*i2+1][0], a0);
                a1 = fma2(lv.y, wu2[2*i2+1][1], a1);
                a2 = fma2(lv.y, wu2[2*i2+1][2], a2);
            }
            size_t o = (size_t)(rowBase + r)*DIMD + tid;
            out[o      ] = lo2(a0) + hi2(a0) + bu3[0];
            out[o + 256] = lo2(a1) + hi2(a1) + bu3[1];
            out[o + 512] = lo2(a2) + hi2(a2) + bu3[2];
        }
    }
}

// ---------------- launch ----------------
extern "C" void kernel_launch(void* const* d_in, const int* in_sizes, int n_in,
                              void* d_out, int out_size) {
    const float* x      = (const float*)d_in[0];
    const float* loc    = (const float*)d_in[1];
    const float* Wd     = (const float*)d_in[2];
    const float* bd     = (const float*)d_in[3];
    const float* Wu     = (const float*)d_in[4];
    const float* bu     = (const float*)d_in[5];
    const float* Wgq    = (const float*)d_in[6];
    const float* bgq    = (const float*)d_in[7];
    const float* Wlq    = (const float*)d_in[8];
    const float* blq    = (const float*)d_in[9];
    const float* ln_c_g = (const float*)d_in[10];
    const float* ln_c_b = (const float*)d_in[11];
    const float* Wc1    = (const float*)d_in[12];
    const float* bc1    = (const float*)d_in[13];
    const float* Wc2    = (const float*)d_in[14];
    const float* bc2    = (const float*)d_in[15];
    const float* ln_g_g = (const float*)d_in[16];
    const float* ln_g_b = (const float*)d_in[17];
    const float* Wg     = (const float*)d_in[18];
    const float* bg     = (const float*)d_in[19];
    float* out = (float*)d_out;

    const size_t smemL = (size_t)(DIMD*LATD)*sizeof(float) + (size_t)KP*ST2*sizeof(float2);
    cudaFuncSetAttribute(latent_kernel, cudaFuncAttributeMaxDynamicSharedMemorySize, (int)smemL);

    latent_kernel<<<(NROWS_X + TILE_ROWS - 1)/TILE_ROWS, 256, smemL>>>(x,   Wd, bd, NROWS_X, 0);
    latent_kernel<<<(NROWS_L + TILE_ROWS - 1)/TILE_ROWS, 256, smemL>>>(loc, Wd, bd, NROWS_L, 1);
    head_kernel<<<BB, 32>>>(ln_c_g, ln_c_b, Wc1, bc1, Wc2, bc2,
                            ln_g_g, ln_g_b, Wg, bg, Wgq, bgq, Wlq, blq);
    attn_part_kernel<<<BB*2*SPLIT, 320>>>();
    attn_combine_kernel<<<BB*NP, 32>>>();
    out_kernel<<<592, 256>>>(Wu, bu, out);
}

// round 6
// speedup vs baseline: 1.2922x; 1.2922x over previous
#include <cuda_runtime.h>
#include <math.h>

#define BB 16
#define SEQ 4107
#define NTOK 4096
#define DIMD 768
#define LATD 20
#define NP 10
#define NROWS_X (BB*SEQ)
#define NROWS_L (BB*NTOK)
#define SPLIT 16
#define CHUNK (NTOK/SPLIT)   // 256

typedef unsigned long long ull;

// ---------------- scratch (device globals: no allocation allowed) ----------------
__device__ __align__(16) float g_xlat[NROWS_X*LATD];   // x latents; prompt rows later overwritten with "enhanced"
__device__ __align__(16) float g_llat[NROWS_L*LATD];   // local latents
__device__ float g_qg[BB*NP*LATD];
__device__ float g_ql[BB*NP*LATD];
__device__ float g_pi[BB*NP];
__device__ float g_gw[BB];
__device__ float g_part[BB*2*NP*SPLIT*22];             // per-split softmax partials: m, s, acc[20]

__device__ __forceinline__ float warp_sum(float v) {
#pragma unroll
    for (int o = 16; o; o >>= 1) v += __shfl_xor_sync(0xffffffffu, v, o);
    return v;
}
__device__ __forceinline__ float warp_max(float v) {
#pragma unroll
    for (int o = 16; o; o >>= 1) v = fmaxf(v, __shfl_xor_sync(0xffffffffu, v, o));
    return v;
}
__device__ __forceinline__ ull fma2(ull a, ull b, ull c) {
    ull d;
    asm("fma.rn.f32x2 %0, %1, %2, %3;" : "=l"(d) : "l"(a), "l"(b), "l"(c));
    return d;
}
__device__ __forceinline__ float lo2(ull v) { float2 f = *(float2*)&v; return f.x; }
__device__ __forceinline__ float hi2(ull v) { float2 f = *(float2*)&v; return f.y; }

// ---------------- Kernel 1: latent = quick_gelu(X @ Wd + bd) ----------------
// f32x2 packed along K + software pipeline: next chunk's LDG issued before the
// compute phase so DRAM latency overlaps the 320-FMA2 inner loop.
#define KC 32
#define KP (KC/2)
#define TILE_ROWS 256
#define ST2 (TILE_ROWS + 1)   // float2 stride per k-pair row

__global__ void __launch_bounds__(256)
latent_kernel(const float* __restrict__ X,
              const float* __restrict__ Wd,
              const float* __restrict__ bd,
              int nRows, int which) {
    extern __shared__ float smem[];
    float*  wds2 = smem;                              // DIMD*LATD floats, pair-interleaved
    float2* xs2  = (float2*)(smem + DIMD*LATD);       // KP * ST2 float2
    float*  dst  = which ? g_llat : g_xlat;

    int tid = threadIdx.x;
    // stage Wd packed: pos = (k/2)*40 + l*2 + (k&1)
    for (int idx = tid; idx < DIMD*LATD; idx += 256) {
        int k = idx / LATD, l = idx - k*LATD;
        wds2[(k >> 1)*40 + l*2 + (k & 1)] = Wd[idx];
    }

    int rowBase = blockIdx.x * TILE_ROWS;
    int myRow = rowBase + tid;

    // this thread's cooperative-load slots (fixed across chunks)
    int slotR[8], slotK[8];
#pragma unroll
    for (int it = 0; it < 8; it++) {
        int i = tid + it*256;
        slotR[it] = i >> 3;       // KC/4 = 8 float4 per row
        slotK[it] = i & 7;
    }

    float4 v[8];
    // prologue: load chunk 0
#pragma unroll
    for (int it = 0; it < 8; it++) {
        int gr = rowBase + slotR[it];
        v[it] = make_float4(0.f, 0.f, 0.f, 0.f);
        if (gr < nRows) v[it] = *(const float4*)(X + (size_t)gr*DIMD + slotK[it]*4);
    }

    ull acc2[LATD];
#pragma unroll
    for (int l = 0; l < LATD; l++) acc2[l] = 0ull;

    for (int kc = 0; kc < DIMD; kc += KC) {
        __syncthreads();   // previous compute done; xs free (also covers Wd staging)
#pragma unroll
        for (int it = 0; it < 8; it++) {
            xs2[(slotK[it]*2    )*ST2 + slotR[it]] = make_float2(v[it].x, v[it].y);
            xs2[(slotK[it]*2 + 1)*ST2 + slotR[it]] = make_float2(v[it].z, v[it].w);
        }
        __syncthreads();   // xs ready
        if (kc + KC < DIMD) {
            // issue next chunk's loads; completion only needed at next STS
#pragma unroll
            for (int it = 0; it < 8; it++) {
                int gr = rowBase + slotR[it];
                v[it] = make_float4(0.f, 0.f, 0.f, 0.f);
                if (gr < nRows) v[it] = *(const float4*)(X + (size_t)gr*DIMD + kc + KC + slotK[it]*4);
            }
        }
#pragma unroll 4
        for (int kp = 0; kp < KP; kp++) {
            ull xv2 = *(const ull*)&xs2[kp*ST2 + tid];
            const ulonglong2* wr = (const ulonglong2*)(wds2 + ((kc >> 1) + kp)*40);
#pragma unroll
            for (int l4 = 0; l4 < 10; l4++) {
                ulonglong2 wv = wr[l4];
                acc2[2*l4    ] = fma2(xv2, wv.x, acc2[2*l4    ]);
                acc2[2*l4 + 1] = fma2(xv2, wv.y, acc2[2*l4 + 1]);
            }
        }
    }

    if (myRow < nRows) {
        float4 o4[5];
        float* ov = (float*)o4;
#pragma unroll
        for (int l = 0; l < LATD; l++) {
            float z = lo2(acc2[l]) + hi2(acc2[l]) + bd[l];
            ov[l] = z * (1.f / (1.f + __expf(-1.702f * z)));   // quick_gelu
        }
        float4* d4 = (float4*)(dst + (size_t)myRow*LATD);
#pragma unroll
        for (int q = 0; q < 5; q++) d4[q] = o4[q];
    }
}

// ---------------- Kernel 2: per-batch head math (1 warp per batch) ----------------
__global__ void __launch_bounds__(32)
head_kernel(const float* __restrict__ ln_c_g, const float* __restrict__ ln_c_b,
            const float* __restrict__ Wc1,    const float* __restrict__ bc1,
            const float* __restrict__ Wc2,    const float* __restrict__ bc2,
            const float* __restrict__ ln_g_g, const float* __restrict__ ln_g_b,
            const float* __restrict__ Wg,     const float* __restrict__ bg,
            const float* __restrict__ Wgq,    const float* __restrict__ bgq,
            const float* __restrict__ Wlq,    const float* __restrict__ blq) {
    int b = blockIdx.x;
    int lane = threadIdx.x;
    __shared__ float pr[NP*LATD];
    __shared__ float clsln[LATD];
    __shared__ float h[64];

    const float* base = g_xlat + (size_t)b*SEQ*LATD;
    for (int i = lane; i < NP*LATD; i += 32) pr[i] = base[i];

    float c = (lane < LATD) ? base[NP*LATD + lane] : 0.f;      // cls latent
    float mu = warp_sum(c) * (1.f/LATD);
    float d = (lane < LATD) ? (c - mu) : 0.f;
    float var = warp_sum(d*d) * (1.f/LATD);
    float rs = rsqrtf(var + 1e-5f);
    if (lane < LATD) clsln[lane] = d*rs*ln_c_g[lane] + ln_c_b[lane];
    __syncwarp();

    // h = gelu_exact(cls_ln @ Wc1 + bc1)
    for (int j = lane; j < 64; j += 32) {
        float s = bc1[j];
#pragma unroll
        for (int l = 0; l < LATD; l++) s = fmaf(clsln[l], Wc1[l*64 + j], s);
        h[j] = 0.5f*s*(1.f + erff(s*0.70710678118654752f));
    }
    __syncwarp();

    // prompt importance = sigmoid(h @ Wc2 + bc2)
    if (lane < NP) {
        float s = bc2[lane];
#pragma unroll
        for (int j = 0; j < 64; j++) s = fmaf(h[j], Wc2[j*NP + lane], s);
        g_pi[b*NP + lane] = 1.f/(1.f + __expf(-s));
    }

    // global weight = sigmoid(LN_g(cls) @ Wg + bg)
    float g2 = (lane < LATD) ? (d*rs*ln_g_g[lane] + ln_g_b[lane]) * Wg[lane] : 0.f;
    float sg = warp_sum(g2);
    if (lane == 0) g_gw[b] = 1.f/(1.f + __expf(-(sg + bg[0])));

    // q projections
    if (lane < LATD) {
        for (int p = 0; p < NP; p++) {
            float sq = bgq[lane], sl = blq[lane];
#pragma unroll
            for (int l = 0; l < LATD; l++) {
                float pv = pr[p*LATD + l];
                sq = fmaf(pv, Wgq[l*LATD + lane], sq);
                sl = fmaf(pv, Wlq[l*LATD + lane], sl);
            }
            g_qg[(b*NP + p)*LATD + lane] = sq;
            g_ql[(b*NP + p)*LATD + lane] = sl;
        }
    }
}

// ---------------- Kernel 3a: split-softmax attention partials ----------------
// grid = BB*2*SPLIT blocks, 320 threads = 10 warps; warp w = prompt w.
// Token chunk staged ONCE in smem in PAIR-MAJOR layout ts2[pair][token]:
// lane stride 8B -> conflict-free LDS.64 (old row-major 80B stride was ~4-way
// conflicted LDS.128). f32x2 dot products and accumulation.
__global__ void __launch_bounds__(320, 2)
attn_part_kernel() {
    int blk = blockIdx.x;
    int b = blk / (2*SPLIT);
    int rem = blk % (2*SPLIT);
    int which = rem / SPLIT;
    int sp = rem % SPLIT;
    int tid = threadIdx.x, w = tid >> 5, lane = tid & 31;

    __shared__ __align__(16) float2 ts2[10*CHUNK];   // 20 KB pair-major
    __shared__ float qs[NP*LATD];

    const float* tok = which
        ? (g_llat + ((size_t)b*NTOK + sp*CHUNK)*LATD)
        : (g_xlat + ((size_t)b*SEQ + NP + 1 + sp*CHUNK)*LATD);
    const float* qsrc = which ? g_ql : g_qg;

    // stage transposed: CHUNK*20 floats = CHUNK*5 float4; 320 threads x 4 each
#pragma unroll
    for (int it = 0; it < (CHUNK*5)/320; it++) {
        int j = tid + it*320;
        int i = j / 5, c = j % 5;         // token i, float4 column-group c
        float4 x4 = ((const float4*)tok)[j];
        ts2[(2*c    )*CHUNK + i] = make_float2(x4.x, x4.y);
        ts2[(2*c + 1)*CHUNK + i] = make_float2(x4.z, x4.w);
    }
    for (int i = tid; i < NP*LATD; i += 320)
        qs[i] = qsrc[(size_t)b*NP*LATD + i];
    __syncthreads();

    const float scale = 0.22360679774997896f;   // LATENT^-0.5
    ull q2[10];
#pragma unroll
    for (int p = 0; p < 10; p++) {
        float2 qq = make_float2(qs[w*LATD + 2*p], qs[w*LATD + 2*p + 1]);
        q2[p] = *(ull*)&qq;
    }

    // pass A: scores for this lane's CHUNK/32 tokens + max
    const int TPL = CHUNK/32;   // 8
    float sc[TPL];
    float m = -1e30f;
#pragma unroll
    for (int t = 0; t < TPL; t++) {
        int idx = t*32 + lane;
        ull s2 = 0ull;
#pragma unroll
        for (int p = 0; p < 10; p++)
            s2 = fma2(*(const ull*)&ts2[p*CHUNK + idx], q2[p], s2);
        sc[t] = (lo2(s2) + hi2(s2)) * scale;
        m = fmaxf(m, sc[t]);
    }
    m = warp_max(m);

    // pass B: exp, sum, weighted accumulation (packed pairs)
    float sum = 0.f;
    ull acc2[10];
#pragma unroll
    for (int p = 0; p < 10; p++) acc2[p] = 0ull;
#pragma unroll
    for (int t = 0; t < TPL; t++) {
        int idx = t*32 + lane;
        float e = __expf(sc[t] - m);
        sum += e;
        float2 ef = make_float2(e, e);
        ull e2 = *(ull*)&ef;
#pragma unroll
        for (int p = 0; p < 10; p++)
            acc2[p] = fma2(e2, *(const ull*)&ts2[p*CHUNK + idx], acc2[p]);
    }
    sum = warp_sum(sum);
    float acc[LATD];
#pragma unroll
    for (int p = 0; p < 10; p++) { acc[2*p] = lo2(acc2[p]); acc[2*p+1] = hi2(acc2[p]); }
#pragma unroll
    for (int l = 0; l < LATD; l++) acc[l] = warp_sum(acc[l]);

    if (lane == 0) {
        float* dst = g_part + ((((size_t)(b*2 + which)*NP + w)*SPLIT + sp)*22);
        dst[0] = m;
        dst[1] = sum;
#pragma unroll
        for (int l = 0; l < LATD; l++) dst[2 + l] = acc[l];
    }
}

// ---------------- Kernel 3b: combine partials + fuse + enhance ----------------
// grid = BB*NP blocks of 32 threads (one warp per (b,p)).
__global__ void __launch_bounds__(32)
attn_combine_kernel() {
    int b = blockIdx.x / NP, p = blockIdx.x % NP;
    int lane = threadIdx.x;
    float ctxv[2];

#pragma unroll
    for (int which = 0; which < 2; which++) {
        const float* base = g_part + (((size_t)(b*2 + which)*NP + p)*SPLIT)*22;
        float mloc = (lane < SPLIT) ? base[lane*22] : -1e30f;
        float M = warp_max(mloc);
        float wfac = (lane < SPLIT) ? __expf(base[lane*22] - M) : 0.f;
        float S = warp_sum((lane < SPLIT) ? wfac * base[lane*22 + 1] : 0.f);
        float a = 0.f;
#pragma unroll
        for (int s = 0; s < SPLIT; s++) {
            float ws = __shfl_sync(0xffffffffu, wfac, s);
            if (lane < LATD) a = fmaf(base[s*22 + 2 + lane], ws, a);
        }
        ctxv[which] = a / S;
    }
    if (lane < LATD) {
        float g = g_gw[b], im = g_pi[b*NP + p];
        g_xlat[((size_t)b*SEQ + p)*LATD + lane] = im * (g*ctxv[0] + (1.f - g)*ctxv[1]);
    }
}

// ---------------- Kernel 4: out = combined @ Wu + bu (f32x2 over l-pairs) ----------------
__global__ void __launch_bounds__(256)
out_kernel(const float* __restrict__ Wu,
           const float* __restrict__ bu,
           float* __restrict__ out) {
    __shared__ __align__(16) float ls[32*LATD];
    int tid = threadIdx.x;

    ull wu2[10][3];
#pragma unroll
    for (int i = 0; i < 10; i++)
#pragma unroll
        for (int c = 0; c < 3; c++) {
            float2 pr = make_float2(Wu[(2*i    )*DIMD + tid + c*256],
                                    Wu[(2*i + 1)*DIMD + tid + c*256]);
            wu2[i][c] = *(ull*)&pr;
        }
    float bu3[3];
#pragma unroll
    for (int c = 0; c < 3; c++) bu3[c] = bu[tid + c*256];

    int nTiles = (NROWS_X + 31) / 32;
    for (int t = blockIdx.x; t < nTiles; t += gridDim.x) {
        int rowBase = t * 32;
        __syncthreads();
#pragma unroll
        for (int it = 0; it < 3; it++) {
            int i = tid + it*256;
            if (i < 32*LATD && (size_t)rowBase*LATD + i < (size_t)NROWS_X*LATD)
                ls[i] = g_xlat[(size_t)rowBase*LATD + i];
        }
        __syncthreads();
        int rmax = min(32, NROWS_X - rowBase);
        for (int r = 0; r < rmax; r++) {
            ull a0 = 0ull, a1 = 0ull, a2 = 0ull;
            const ulonglong2* lr = (const ulonglong2*)(ls + r*LATD);   // 5 x LDS.128 broadcast
#pragma unroll
            for (int i2 = 0; i2 < 5; i2++) {
                ulonglong2 lv = lr[i2];
                a0 = fma2(lv.x, wu2[2*i2][0], a0);
                a1 = fma2(lv.x, wu2[2*i2][1], a1);
                a2 = fma2(lv.x, wu2[2*i2][2], a2);
                a0 = fma2(lv.y, wu2[2*i2+1][0], a0);
                a1 = fma2(lv.y, wu2[2*i2+1][1], a1);
                a2 = fma2(lv.y, wu2[2*i2+1][2], a2);
            }
            size_t o = (size_t)(rowBase + r)*DIMD + tid;
            out[o      ] = lo2(a0) + hi2(a0) + bu3[0];
            out[o + 256] = lo2(a1) + hi2(a1) + bu3[1];
            out[o + 512] = lo2(a2) + hi2(a2) + bu3[2];
        }
    }
}

// ---------------- launch ----------------
extern "C" void kernel_launch(void* const* d_in, const int* in_sizes, int n_in,
                              void* d_out, int out_size) {
    const float* x      = (const float*)d_in[0];
    const float* loc    = (const float*)d_in[1];
    const float* Wd     = (const float*)d_in[2];
    const float* bd     = (const float*)d_in[3];
    const float* Wu     = (const float*)d_in[4];
    const float* bu     = (const float*)d_in[5];
    const float* Wgq    = (const float*)d_in[6];
    const float* bgq    = (const float*)d_in[7];
    const float* Wlq    = (const float*)d_in[8];
    const float* blq    = (const float*)d_in[9];
    const float* ln_c_g = (const float*)d_in[10];
    const float* ln_c_b = (const float*)d_in[11];
    const float* Wc1    = (const float*)d_in[12];
    const float* bc1    = (const float*)d_in[13];
    const float* Wc2    = (const float*)d_in[14];
    const float* bc2    = (const float*)d_in[15];
    const float* ln_g_g = (const float*)d_in[16];
    const float* ln_g_b = (const float*)d_in[17];
    const float* Wg     = (const float*)d_in[18];
    const float* bg     = (const float*)d_in[19];
    float* out = (float*)d_out;

    const size_t smemL = (size_t)(DIMD*LATD)*sizeof(float) + (size_t)KP*ST2*sizeof(float2);
    cudaFuncSetAttribute(latent_kernel, cudaFuncAttributeMaxDynamicSharedMemorySize, (int)smemL);

    latent_kernel<<<(NROWS_X + TILE_ROWS - 1)/TILE_ROWS, 256, smemL>>>(x,   Wd, bd, NROWS_X, 0);
    latent_kernel<<<(NROWS_L + TILE_ROWS - 1)/TILE_ROWS, 256, smemL>>>(loc, Wd, bd, NROWS_L, 1);
    head_kernel<<<BB, 32>>>(ln_c_g, ln_c_b, Wc1, bc1, Wc2, bc2,
                            ln_g_g, ln_g_b, Wg, bg, Wgq, bgq, Wlq, blq);
    attn_part_kernel<<<BB*2*SPLIT, 320>>>();
    attn_combine_kernel<<<BB*NP, 32>>>();
    out_kernel<<<592, 256>>>(Wu, bu, out);
}

// round 7
// speedup vs baseline: 1.3820x; 1.0695x over previous
#include <cuda_runtime.h>
#include <math.h>

#define BB 16
#define SEQ 4107
#define NTOK 4096
#define DIMD 768
#define LATD 20
#define NP 10
#define NROWS_X (BB*SEQ)
#define NROWS_L (BB*NTOK)
#define SPLIT 32
#define CHUNK (NTOK/SPLIT)   // 128

typedef unsigned long long ull;

// ---------------- scratch (device globals: no allocation allowed) ----------------
__device__ __align__(16) float g_xlat[NROWS_X*LATD];   // x latents; prompt rows later overwritten with "enhanced"
__device__ __align__(16) float g_llat[NROWS_L*LATD];   // local latents
__device__ float g_qg[BB*NP*LATD];
__device__ float g_ql[BB*NP*LATD];
__device__ float g_pi[BB*NP];
__device__ float g_gw[BB];
__device__ float g_part[BB*2*NP*SPLIT*22];             // per-split softmax partials: m, s, acc[20]

__device__ __forceinline__ float warp_sum(float v) {
#pragma unroll
    for (int o = 16; o; o >>= 1) v += __shfl_xor_sync(0xffffffffu, v, o);
    return v;
}
__device__ __forceinline__ float warp_max(float v) {
#pragma unroll
    for (int o = 16; o; o >>= 1) v = fmaxf(v, __shfl_xor_sync(0xffffffffu, v, o));
    return v;
}
__device__ __forceinline__ ull fma2(ull a, ull b, ull c) {
    ull d;
    asm("fma.rn.f32x2 %0, %1, %2, %3;" : "=l"(d) : "l"(a), "l"(b), "l"(c));
    return d;
}
__device__ __forceinline__ ull dup2(float x) {
    ull d;
    asm("mov.b64 %0, {%1, %1};" : "=l"(d) : "f"(x));
    return d;
}
__device__ __forceinline__ float lo2(ull v) { float2 f = *(float2*)&v; return f.x; }
__device__ __forceinline__ float hi2(ull v) { float2 f = *(float2*)&v; return f.y; }

// ---------------- Kernel 1: latent = quick_gelu(X @ Wd + bd), both tensors ----------------
// R=2 rows/thread, l-packed f32x2 accumulators (10 ull/row), weights read as
// natural row-major pairs (5 broadcast LDS.128 per k), x duplicated via mov.b64.
// Per k per warp: 2 LDS.32 + 2 pack + 5 LDS.128 + 20 FMA2 -> FMA-pipe bound.
// Software pipeline: next chunk's LDG overlaps compute. One merged grid.
#define KC 16
#define TR 512
#define ST (TR + 1)
#define NBX ((NROWS_X + TR - 1)/TR)   // 129

__global__ void __launch_bounds__(256, 2)
latent_kernel(const float* __restrict__ X0,
              const float* __restrict__ X1,
              const float* __restrict__ Wd,
              const float* __restrict__ bd) {
    extern __shared__ float smem[];
    float* wds = smem;                 // DIMD*LATD floats, row-major copy
    float* xs  = smem + DIMD*LATD;     // KC * ST floats, xs[k][row]

    int tid = threadIdx.x;
    int which = (blockIdx.x >= NBX);
    const float* X = which ? X1 : X0;
    float* dst = which ? g_llat : g_xlat;
    int nRows = which ? NROWS_L : NROWS_X;
    int rowBase = (which ? (blockIdx.x - NBX) : blockIdx.x) * TR;

    // stage Wd (plain copy)
    for (int i = tid; i < DIMD*LATD/4; i += 256)
        ((float4*)wds)[i] = ((const float4*)Wd)[i];

    // cooperative-load slots: 512 rows x 16 floats = 2048 float4, 8 per thread
    int slotR[8], slotK[8];
#pragma unroll
    for (int it = 0; it < 8; it++) {
        int i = tid + it*256;
        slotR[it] = i >> 2;       // 4 float4 per row
        slotK[it] = i & 3;
    }

    float4 v[8];
#pragma unroll
    for (int it = 0; it < 8; it++) {
        int gr = rowBase + slotR[it];
        v[it] = make_float4(0.f, 0.f, 0.f, 0.f);
        if (gr < nRows) v[it] = *(const float4*)(X + (size_t)gr*DIMD + slotK[it]*4);
    }

    ull acca[10], accb[10];
#pragma unroll
    for (int j = 0; j < 10; j++) { acca[j] = 0ull; accb[j] = 0ull; }

    for (int kc = 0; kc < DIMD; kc += KC) {
        __syncthreads();   // previous compute done (also covers Wd staging on iter 0)
#pragma unroll
        for (int it = 0; it < 8; it++) {
            int base = (slotK[it]*4)*ST + slotR[it];
            xs[base       ] = v[it].x;
            xs[base + ST  ] = v[it].y;
            xs[base + 2*ST] = v[it].z;
            xs[base + 3*ST] = v[it].w;
        }
        __syncthreads();   // xs ready
        if (kc + KC < DIMD) {
#pragma unroll
            for (int it = 0; it < 8; it++) {
                int gr = rowBase + slotR[it];
                v[it] = make_float4(0.f, 0.f, 0.f, 0.f);
                if (gr < nRows) v[it] = *(const float4*)(X + (size_t)gr*DIMD + kc + KC + slotK[it]*4);
            }
        }
#pragma unroll
        for (int k = 0; k < KC; k++) {
            ull xa2 = dup2(xs[k*ST + tid]);
            ull xb2 = dup2(xs[k*ST + 256 + tid]);
            const ulonglong2* wr = (const ulonglong2*)(wds + (kc + k)*LATD);
#pragma unroll
            for (int j2 = 0; j2 < 5; j2++) {
                ulonglong2 w2 = wr[j2];
                acca[2*j2    ] = fma2(xa2, w2.x, acca[2*j2    ]);
                acca[2*j2 + 1] = fma2(xa2, w2.y, acca[2*j2 + 1]);
                accb[2*j2    ] = fma2(xb2, w2.x, accb[2*j2    ]);
                accb[2*j2 + 1] = fma2(xb2, w2.y, accb[2*j2 + 1]);
            }
        }
    }

    // epilogue: bias + quick_gelu + store (rows tid and tid+256)
#pragma unroll
    for (int rr = 0; rr < 2; rr++) {
        int myRow = rowBase + rr*256 + tid;
        if (myRow >= nRows) continue;
        ull* acc = rr ? accb : acca;
        float4 o4[5];
        float* ov = (float*)o4;
#pragma unroll
        for (int j = 0; j < 10; j++) {
            float z0 = lo2(acc[j]) + bd[2*j];
            float z1 = hi2(acc[j]) + bd[2*j + 1];
            ov[2*j    ] = z0 * (1.f / (1.f + __expf(-1.702f * z0)));
            ov[2*j + 1] = z1 * (1.f / (1.f + __expf(-1.702f * z1)));
        }
        float4* d4 = (float4*)(dst + (size_t)myRow*LATD);
#pragma unroll
        for (int q = 0; q < 5; q++) d4[q] = o4[q];
    }
}

// ---------------- Kernel 2: per-batch head math (1 warp per batch) ----------------
__global__ void __launch_bounds__(32)
head_kernel(const float* __restrict__ ln_c_g, const float* __restrict__ ln_c_b,
            const float* __restrict__ Wc1,    const float* __restrict__ bc1,
            const float* __restrict__ Wc2,    const float* __restrict__ bc2,
            const float* __restrict__ ln_g_g, const float* __restrict__ ln_g_b,
            const float* __restrict__ Wg,     const float* __restrict__ bg,
            const float* __restrict__ Wgq,    const float* __restrict__ bgq,
            const float* __restrict__ Wlq,    const float* __restrict__ blq) {
    int b = blockIdx.x;
    int lane = threadIdx.x;
    __shared__ float pr[NP*LATD];
    __shared__ float clsln[LATD];
    __shared__ float h[64];

    const float* base = g_xlat + (size_t)b*SEQ*LATD;
    for (int i = lane; i < NP*LATD; i += 32) pr[i] = base[i];

    float c = (lane < LATD) ? base[NP*LATD + lane] : 0.f;      // cls latent
    float mu = warp_sum(c) * (1.f/LATD);
    float d = (lane < LATD) ? (c - mu) : 0.f;
    float var = warp_sum(d*d) * (1.f/LATD);
    float rs = rsqrtf(var + 1e-5f);
    if (lane < LATD) clsln[lane] = d*rs*ln_c_g[lane] + ln_c_b[lane];
    __syncwarp();

    // h = gelu_exact(cls_ln @ Wc1 + bc1)
    for (int j = lane; j < 64; j += 32) {
        float s = bc1[j];
#pragma unroll
        for (int l = 0; l < LATD; l++) s = fmaf(clsln[l], Wc1[l*64 + j], s);
        h[j] = 0.5f*s*(1.f + erff(s*0.70710678118654752f));
    }
    __syncwarp();

    // prompt importance = sigmoid(h @ Wc2 + bc2)
    if (lane < NP) {
        float s = bc2[lane];
#pragma unroll
        for (int j = 0; j < 64; j++) s = fmaf(h[j], Wc2[j*NP + lane], s);
        g_pi[b*NP + lane] = 1.f/(1.f + __expf(-s));
    }

    // global weight = sigmoid(LN_g(cls) @ Wg + bg)
    float g2 = (lane < LATD) ? (d*rs*ln_g_g[lane] + ln_g_b[lane]) * Wg[lane] : 0.f;
    float sg = warp_sum(g2);
    if (lane == 0) g_gw[b] = 1.f/(1.f + __expf(-(sg + bg[0])));

    // q projections
    if (lane < LATD) {
        for (int p = 0; p < NP; p++) {
            float sq = bgq[lane], sl = blq[lane];
#pragma unroll
            for (int l = 0; l < LATD; l++) {
                float pv = pr[p*LATD + l];
                sq = fmaf(pv, Wgq[l*LATD + lane], sq);
                sl = fmaf(pv, Wlq[l*LATD + lane], sl);
            }
            g_qg[(b*NP + p)*LATD + lane] = sq;
            g_ql[(b*NP + p)*LATD + lane] = sl;
        }
    }
}

// ---------------- Kernel 3a: split-softmax attention partials ----------------
// grid = BB*2*SPLIT blocks, 320 threads = 10 warps; warp w = prompt w.
// Token chunk staged ONCE in smem pair-major ts2[pair][token] (conflict-free LDS.64).
__global__ void __launch_bounds__(320, 2)
attn_part_kernel() {
    int blk = blockIdx.x;
    int b = blk / (2*SPLIT);
    int rem = blk % (2*SPLIT);
    int which = rem / SPLIT;
    int sp = rem % SPLIT;
    int tid = threadIdx.x, w = tid >> 5, lane = tid & 31;

    __shared__ __align__(16) float2 ts2[10*CHUNK];   // 10 KB pair-major
    __shared__ float qs[NP*LATD];

    const float* tok = which
        ? (g_llat + ((size_t)b*NTOK + sp*CHUNK)*LATD)
        : (g_xlat + ((size_t)b*SEQ + NP + 1 + sp*CHUNK)*LATD);
    const float* qsrc = which ? g_ql : g_qg;

    // stage transposed: CHUNK*20 floats = CHUNK*5 float4
#pragma unroll
    for (int it = 0; it < (CHUNK*5)/320; it++) {
        int j = tid + it*320;
        int i = j / 5, c = j % 5;         // token i, float4 column-group c
        float4 x4 = ((const float4*)tok)[j];
        ts2[(2*c    )*CHUNK + i] = make_float2(x4.x, x4.y);
        ts2[(2*c + 1)*CHUNK + i] = make_float2(x4.z, x4.w);
    }
    for (int i = tid; i < NP*LATD; i += 320)
        qs[i] = qsrc[(size_t)b*NP*LATD + i];
    __syncthreads();

    const float scale = 0.22360679774997896f;   // LATENT^-0.5
    ull q2[10];
#pragma unroll
    for (int p = 0; p < 10; p++) {
        float2 qq = make_float2(qs[w*LATD + 2*p], qs[w*LATD + 2*p + 1]);
        q2[p] = *(ull*)&qq;
    }

    // pass A: scores for this lane's CHUNK/32 tokens + max
    const int TPL = CHUNK/32;   // 4
    float sc[TPL];
    float m = -1e30f;
#pragma unroll
    for (int t = 0; t < TPL; t++) {
        int idx = t*32 + lane;
        ull s2 = 0ull;
#pragma unroll
        for (int p = 0; p < 10; p++)
            s2 = fma2(*(const ull*)&ts2[p*CHUNK + idx], q2[p], s2);
        sc[t] = (lo2(s2) + hi2(s2)) * scale;
        m = fmaxf(m, sc[t]);
    }
    m = warp_max(m);

    // pass B: exp, sum, weighted accumulation (packed pairs)
    float sum = 0.f;
    ull acc2[10];
#pragma unroll
    for (int p = 0; p < 10; p++) acc2[p] = 0ull;
#pragma unroll
    for (int t = 0; t < TPL; t++) {
        int idx = t*32 + lane;
        float e = __expf(sc[t] - m);
        sum += e;
        ull e2 = dup2(e);
#pragma unroll
        for (int p = 0; p < 10; p++)
            acc2[p] = fma2(e2, *(const ull*)&ts2[p*CHUNK + idx], acc2[p]);
    }
    sum = warp_sum(sum);
    float acc[LATD];
#pragma unroll
    for (int p = 0; p < 10; p++) { acc[2*p] = lo2(acc2[p]); acc[2*p+1] = hi2(acc2[p]); }
#pragma unroll
    for (int l = 0; l < LATD; l++) acc[l] = warp_sum(acc[l]);

    if (lane == 0) {
        float* dst = g_part + ((((size_t)(b*2 + which)*NP + w)*SPLIT + sp)*22);
        dst[0] = m;
        dst[1] = sum;
#pragma unroll
        for (int l = 0; l < LATD; l++) dst[2 + l] = acc[l];
    }
}

// ---------------- Kernel 3b: combine partials + fuse + enhance ----------------
__global__ void __launch_bounds__(32)
attn_combine_kernel() {
    int b = blockIdx.x / NP, p = blockIdx.x % NP;
    int lane = threadIdx.x;
    float ctxv[2];

#pragma unroll
    for (int which = 0; which < 2; which++) {
        const float* base = g_part + (((size_t)(b*2 + which)*NP + p)*SPLIT)*22;
        float mloc = (lane < SPLIT) ? base[lane*22] : -1e30f;
        float M = warp_max(mloc);
        float wfac = (lane < SPLIT) ? __expf(base[lane*22] - M) : 0.f;
        float S = warp_sum((lane < SPLIT) ? wfac * base[lane*22 + 1] : 0.f);
        float a = 0.f;
#pragma unroll
        for (int s = 0; s < SPLIT; s++) {
            float ws = __shfl_sync(0xffffffffu, wfac, s);
            if (lane < LATD) a = fmaf(base[s*22 + 2 + lane], ws, a);
        }
        ctxv[which] = a / S;
    }
    if (lane < LATD) {
        float g = g_gw[b], im = g_pi[b*NP + p];
        g_xlat[((size_t)b*SEQ + p)*LATD + lane] = im * (g*ctxv[0] + (1.f - g)*ctxv[1]);
    }
}

// ---------------- Kernel 4: out = combined @ Wu + bu ----------------
// 192 threads, 4 contiguous cols/thread -> one STG.128 per row per thread.
// Wu held as l-packed pairs in 80 regs; latent row read as 5 broadcast LDS.128.
__global__ void __launch_bounds__(192)
out_kernel(const float* __restrict__ Wu,
           const float* __restrict__ bu,
           float* __restrict__ out) {
    __shared__ __align__(16) float ls[32*LATD];
    int tid = threadIdx.x;
    int c0 = tid*4;

    ull wu2[10][4];
#pragma unroll
    for (int j = 0; j < 10; j++)
#pragma unroll
        for (int c = 0; c < 4; c++) {
            float2 pr = make_float2(Wu[(2*j    )*DIMD + c0 + c],
                                    Wu[(2*j + 1)*DIMD + c0 + c]);
            wu2[j][c] = *(ull*)&pr;
        }
    float bu4[4];
#pragma unroll
    for (int c = 0; c < 4; c++) bu4[c] = bu[c0 + c];

    int nTiles = (NROWS_X + 31) / 32;
    for (int t = blockIdx.x; t < nTiles; t += gridDim.x) {
        int rowBase = t * 32;
        int rmax = min(32, NROWS_X - rowBase);
        __syncthreads();
        for (int i = tid; i < rmax*LATD; i += 192)
            ls[i] = g_xlat[(size_t)rowBase*LATD + i];
        __syncthreads();
        for (int r = 0; r < rmax; r++) {
            const ulonglong2* lr = (const ulonglong2*)(ls + r*LATD);   // broadcast
            ull a0 = 0ull, a1 = 0ull, a2 = 0ull, a3 = 0ull;
#pragma unroll
            for (int j2 = 0; j2 < 5; j2++) {
                ulonglong2 lv = lr[j2];
                a0 = fma2(lv.x, wu2[2*j2][0], a0);
                a1 = fma2(lv.x, wu2[2*j2][1], a1);
                a2 = fma2(lv.x, wu2[2*j2][2], a2);
                a3 = fma2(lv.x, wu2[2*j2][3], a3);
                a0 = fma2(lv.y, wu2[2*j2+1][0], a0);
                a1 = fma2(lv.y, wu2[2*j2+1][1], a1);
                a2 = fma2(lv.y, wu2[2*j2+1][2], a2);
                a3 = fma2(lv.y, wu2[2*j2+1][3], a3);
            }
            float4 o;
            o.x = lo2(a0) + hi2(a0) + bu4[0];
            o.y = lo2(a1) + hi2(a1) + bu4[1];
            o.z = lo2(a2) + hi2(a2) + bu4[2];
            o.w = lo2(a3) + hi2(a3) + bu4[3];
            *(float4*)(out + (size_t)(rowBase + r)*DIMD + c0) = o;
        }
    }
}

// ---------------- launch ----------------
extern "C" void kernel_launch(void* const* d_in, const int* in_sizes, int n_in,
                              void* d_out, int out_size) {
    const float* x      = (const float*)d_in[0];
    const float* loc    = (const float*)d_in[1];
    const float* Wd     = (const float*)d_in[2];
    const float* bd     = (const float*)d_in[3];
    const float* Wu     = (const float*)d_in[4];
    const float* bu     = (const float*)d_in[5];
    const float* Wgq    = (const float*)d_in[6];
    const float* bgq    = (const float*)d_in[7];
    const float* Wlq    = (const float*)d_in[8];
    const float* blq    = (const float*)d_in[9];
    const float* ln_c_g = (const float*)d_in[10];
    const float* ln_c_b = (const float*)d_in[11];
    const float* Wc1    = (const float*)d_in[12];
    const float* bc1    = (const float*)d_in[13];
    const float* Wc2    = (const float*)d_in[14];
    const float* bc2    = (const float*)d_in[15];
    const float* ln_g_g = (const float*)d_in[16];
    const float* ln_g_b = (const float*)d_in[17];
    const float* Wg     = (const float*)d_in[18];
    const float* bg     = (const float*)d_in[19];
    float* out = (float*)d_out;

    const int NBL = (NROWS_L + TR - 1)/TR;   // 128
    const size_t smemL = (size_t)(DIMD*LATD + KC*ST) * sizeof(float);
    cudaFuncSetAttribute(latent_kernel, cudaFuncAttributeMaxDynamicSharedMemorySize, (int)smemL);

    latent_kernel<<<NBX + NBL, 256, smemL>>>(x, loc, Wd, bd);
    head_kernel<<<BB, 32>>>(ln_c_g, ln_c_b, Wc1, bc1, Wc2, bc2,
                            ln_g_g, ln_g_b, Wg, bg, Wgq, bgq, Wlq, blq);
    attn_part_kernel<<<BB*2*SPLIT, 320>>>();
    attn_combine_kernel<<<BB*NP, 32>>>();
    out_kernel<<<444, 192>>>(Wu, bu, out);
}

// round 9
// speedup vs baseline: 1.7826x; 1.2899x over previous
#include <cuda_runtime.h>
#include <cuda_bf16.h>
#include <math.h>

#define BB 16
#define SEQ 4107
#define NTOK 4096
#define DIMD 768
#define LATD 20
#define NP 10
#define NROWS_X (BB*SEQ)
#define NROWS_L (BB*NTOK)
#define SPLIT 32
#define CHUNK (NTOK/SPLIT)   // 128

// latent mma kernel tiling
#define NTX ((NROWS_X + 127)/128)   // 514
#define NTL (NROWS_L/128)           // 512
#define KCH 128
#define NCH (DIMD/KCH)               // 6

// smem byte offsets (A rows padded to 136 bf16 = 272B; B rows padded to 776 bf16)
#define SM_A_HI 0
#define SM_A_LO 34816
#define SM_B_HI 69632
#define SM_B_LO 106880
#define SMEM_MMA_TOTAL 144128

typedef unsigned long long ull;

// ---------------- scratch (device globals: no allocation allowed) ----------------
__device__ __align__(16) float g_xlat[NROWS_X*LATD];
__device__ __align__(16) float g_llat[NROWS_L*LATD];
__device__ float g_qg[BB*NP*LATD];
__device__ float g_ql[BB*NP*LATD];
__device__ float g_pi[BB*NP];
__device__ float g_gw[BB];
__device__ float g_part[BB*2*NP*SPLIT*22];

__device__ __forceinline__ float warp_sum(float v) {
#pragma unroll
    for (int o = 16; o; o >>= 1) v += __shfl_xor_sync(0xffffffffu, v, o);
    return v;
}
__device__ __forceinline__ float warp_max(float v) {
#pragma unroll
    for (int o = 16; o; o >>= 1) v = fmaxf(v, __shfl_xor_sync(0xffffffffu, v, o));
    return v;
}
__device__ __forceinline__ ull fma2(ull a, ull b, ull c) {
    ull d;
    asm("fma.rn.f32x2 %0, %1, %2, %3;" : "=l"(d) : "l"(a), "l"(b), "l"(c));
    return d;
}
__device__ __forceinline__ ull dup2(float x) {
    ull d;
    asm("mov.b64 %0, {%1, %1};" : "=l"(d) : "f"(x));
    return d;
}
__device__ __forceinline__ float lo2(ull v) { float2 f = *(float2*)&v; return f.x; }
__device__ __forceinline__ float hi2(ull v) { float2 f = *(float2*)&v; return f.y; }

// ---------------- mma.sync helpers (sm_80 baseline -> OK on plain sm_103 target) ----------------
__device__ __forceinline__ unsigned smem_u32(const void* p) {
    unsigned a;
    asm("{ .reg .u64 t; cvta.to.shared.u64 t, %1; cvt.u32.u64 %0, t; }" : "=r"(a) : "l"(p));
    return a;
}
__device__ __forceinline__ void ldsm4(unsigned& r0, unsigned& r1, unsigned& r2, unsigned& r3, unsigned addr) {
    asm volatile("ldmatrix.sync.aligned.m8n8.x4.shared.b16 {%0,%1,%2,%3}, [%4];"
                 : "=r"(r0), "=r"(r1), "=r"(r2), "=r"(r3) : "r"(addr));
}
__device__ __forceinline__ void ldsm2(unsigned& r0, unsigned& r1, unsigned addr) {
    asm volatile("ldmatrix.sync.aligned.m8n8.x2.shared.b16 {%0,%1}, [%2];"
                 : "=r"(r0), "=r"(r1) : "r"(addr));
}
__device__ __forceinline__ void mma_bf16(float* d, const unsigned* a, unsigned b0, unsigned b1) {
    asm volatile(
        "mma.sync.aligned.m16n8k16.row.col.f32.bf16.bf16.f32 "
        "{%0,%1,%2,%3}, {%4,%5,%6,%7}, {%8,%9}, {%0,%1,%2,%3};"
        : "+f"(d[0]), "+f"(d[1]), "+f"(d[2]), "+f"(d[3])
        : "r"(a[0]), "r"(a[1]), "r"(a[2]), "r"(a[3]), "r"(b0), "r"(b1));
}
// split fp32 pair -> bf16x2 hi (rn) + bf16x2 lo (rn of residual)
__device__ __forceinline__ void split2(float x0, float x1, unsigned& hi, unsigned& lo) {
    asm("cvt.rn.bf16x2.f32 %0, %1, %2;" : "=r"(hi) : "f"(x1), "f"(x0));
    unsigned e0, e1;
    asm("prmt.b32 %0, %1, %2, 0x1044;" : "=r"(e0) : "r"(hi), "r"(0u));
    asm("prmt.b32 %0, %1, %2, 0x3244;" : "=r"(e1) : "r"(hi), "r"(0u));
    float r0 = x0 - __uint_as_float(e0);
    float r1 = x1 - __uint_as_float(e1);
    asm("cvt.rn.bf16x2.f32 %0, %1, %2;" : "=r"(lo) : "f"(r1), "f"(r0));
}

// ---------------- Kernel 1: latent = quick_gelu(X @ Wd + bd) via HMMA ----------------
// Block = 256 thr = 8 warps; block tile M=128 rows, warp tile 16 rows x 24 cols (N pad).
// K=768 in 6 chunks of 128. fp32 split into bf16 hi+lo; 3 mma products into f32 acc.
__device__ __forceinline__ void ldg_chunk(float4* v, const float* __restrict__ X,
                                          int rowBase, int nRows, int c, int tid) {
#pragma unroll
    for (int it = 0; it < 16; it++) {
        int i = tid + it*256;
        int r = i >> 5, c4 = i & 31;
        int gr = rowBase + r;
        v[it] = make_float4(0.f, 0.f, 0.f, 0.f);
        if (gr < nRows) v[it] = *(const float4*)(X + (size_t)gr*DIMD + c*KCH + c4*4);
    }
}
__device__ __forceinline__ void sts_chunk(char* smem, const float4* v, int tid) {
#pragma unroll
    for (int it = 0; it < 16; it++) {
        int i = tid + it*256;
        int r = i >> 5, c4 = i & 31;
        float4 x4 = v[it];
        unsigned h01, l01, h23, l23;
        split2(x4.x, x4.y, h01, l01);
        split2(x4.z, x4.w, h23, l23);
        int off = r*272 + c4*8;
        *(uint2*)(smem + SM_A_HI + off) = make_uint2(h01, h23);
        *(uint2*)(smem + SM_A_LO + off) = make_uint2(l01, l23);
    }
}

__global__ void __launch_bounds__(256, 1)
latent_mma_kernel(const float* __restrict__ X0, const float* __restrict__ X1,
                  const float* __restrict__ Wd, const float* __restrict__ bd) {
    extern __shared__ char smem[];
    unsigned sb = smem_u32(smem);
    int tid = threadIdx.x, lane = tid & 31, w = tid >> 5;
    int gid = lane >> 2, tig = lane & 3;

    int which = (blockIdx.x >= NTX);
    const float* X = which ? X1 : X0;
    float* dst = which ? g_llat : g_xlat;
    int nRows = which ? NROWS_L : NROWS_X;
    int rowBase = (which ? (int)blockIdx.x - NTX : (int)blockIdx.x) * 128;

    // prologue LDG for chunk 0 (overlaps B staging)
    float4 v[16];
    ldg_chunk(v, X, rowBase, nRows, 0, tid);

    // stage B = Wd^T as [n=24][k=768] bf16 hi/lo, row stride 776
    for (int idx = tid; idx < 4*DIMD; idx += 256) {           // zero rows n=20..23
        int n = 20 + (idx >> 9)*0 + idx / DIMD, k = idx % DIMD;
        int off = (n*776 + k)*2;
        *(unsigned short*)(smem + SM_B_HI + off) = 0;
        *(unsigned short*)(smem + SM_B_LO + off) = 0;
    }
    for (int idx = tid; idx < DIMD*LATD; idx += 256) {
        int k = idx / LATD, n = idx - k*LATD;
        float xv = Wd[idx];
        unsigned hi, lo;
        split2(xv, 0.f, hi, lo);
        int off = (n*776 + k)*2;
        *(unsigned short*)(smem + SM_B_HI + off) = (unsigned short)(hi & 0xFFFFu);
        *(unsigned short*)(smem + SM_B_LO + off) = (unsigned short)(lo & 0xFFFFu);
    }

    sts_chunk(smem, v, tid);
    __syncthreads();

    // per-thread ldmatrix base offsets
    unsigned aRow = w*16 + (lane & 7) + ((lane >> 3) & 1)*8;
    unsigned aOff = aRow*272 + ((lane >> 4)*8)*2;                    // bytes rel SM_A_*
    unsigned bN4  = ((lane & 7) + ((lane >> 4) & 1)*8);
    unsigned bOff4 = bN4*1552 + (((lane >> 3) & 1)*8)*2;             // bytes rel SM_B_*
    unsigned bN2  = 16 + (lane & 7);
    unsigned bOff2 = bN2*1552 + (((lane >> 3) & 1)*8)*2;

    float acc[3][4];
#pragma unroll
    for (int f = 0; f < 3; f++)
#pragma unroll
        for (int q = 0; q < 4; q++) acc[f][q] = 0.f;

    for (int c = 0; c < NCH; c++) {
        if (c + 1 < NCH) ldg_chunk(v, X, rowBase, nRows, c + 1, tid);
#pragma unroll
        for (int ks = 0; ks < 8; ks++) {
            unsigned ah[4], al[4], bh[4], bl[4], bh2[2], bl2[2];
            unsigned aA = sb + SM_A_HI + aOff + ks*32;
            ldsm4(ah[0], ah[1], ah[2], ah[3], aA);
            ldsm4(al[0], al[1], al[2], al[3], aA + (SM_A_LO - SM_A_HI));
            unsigned kb = (unsigned)(c*KCH + ks*16)*2;
            unsigned bA = sb + SM_B_HI + bOff4 + kb;
            ldsm4(bh[0], bh[1], bh[2], bh[3], bA);
            ldsm4(bl[0], bl[1], bl[2], bl[3], bA + (SM_B_LO - SM_B_HI));
            ldsm2(bh2[0], bh2[1], sb + SM_B_HI + bOff2 + kb);
            ldsm2(bl2[0], bl2[1], sb + SM_B_LO + bOff2 + kb);

            mma_bf16(acc[0], ah, bh[0], bh[1]);
            mma_bf16(acc[0], al, bh[0], bh[1]);
            mma_bf16(acc[0], ah, bl[0], bl[1]);
            mma_bf16(acc[1], ah, bh[2], bh[3]);
            mma_bf16(acc[1], al, bh[2], bh[3]);
            mma_bf16(acc[1], ah, bl[2], bl[3]);
            mma_bf16(acc[2], ah, bh2[0], bh2[1]);
            mma_bf16(acc[2], al, bh2[0], bh2[1]);
            mma_bf16(acc[2], ah, bl2[0], bl2[1]);
        }
        __syncthreads();
        if (c + 1 < NCH) {
            sts_chunk(smem, v, tid);
            __syncthreads();
        }
    }

    // epilogue: bias + quick_gelu + store
    int r0 = rowBase + w*16 + gid;
#pragma unroll
    for (int f = 0; f < 3; f++) {
        int col = f*8 + tig*2;
        if (col >= LATD) continue;
        float b0 = bd[col], b1 = bd[col + 1];
#pragma unroll
        for (int half = 0; half < 2; half++) {
            int row = r0 + half*8;
            if (row < nRows) {
                float z0 = acc[f][half*2]     + b0;
                float z1 = acc[f][half*2 + 1] + b1;
                float2 o;
                o.x = z0 * (1.f / (1.f + __expf(-1.702f * z0)));
                o.y = z1 * (1.f / (1.f + __expf(-1.702f * z1)));
                *(float2*)(dst + (size_t)row*LATD + col) = o;
            }
        }
    }
}

// ---------------- Kernel 2: per-batch head math (1 warp per batch) ----------------
__global__ void __launch_bounds__(32)
head_kernel(const float* __restrict__ ln_c_g, const float* __restrict__ ln_c_b,
            const float* __restrict__ Wc1,    const float* __restrict__ bc1,
            const float* __restrict__ Wc2,    const float* __restrict__ bc2,
            const float* __restrict__ ln_g_g, const float* __restrict__ ln_g_b,
            const float* __restrict__ Wg,     const float* __restrict__ bg,
            const float* __restrict__ Wgq,    const float* __restrict__ bgq,
            const float* __restrict__ Wlq,    const float* __restrict__ blq) {
    int b = blockIdx.x;
    int lane = threadIdx.x;
    __shared__ float pr[NP*LATD];
    __shared__ float clsln[LATD];
    __shared__ float h[64];

    const float* base = g_xlat + (size_t)b*SEQ*LATD;
    for (int i = lane; i < NP*LATD; i += 32) pr[i] = base[i];

    float c = (lane < LATD) ? base[NP*LATD + lane] : 0.f;
    float mu = warp_sum(c) * (1.f/LATD);
    float d = (lane < LATD) ? (c - mu) : 0.f;
    float var = warp_sum(d*d) * (1.f/LATD);
    float rs = rsqrtf(var + 1e-5f);
    if (lane < LATD) clsln[lane] = d*rs*ln_c_g[lane] + ln_c_b[lane];
    __syncwarp();

    for (int j = lane; j < 64; j += 32) {
        float s = bc1[j];
#pragma unroll
        for (int l = 0; l < LATD; l++) s = fmaf(clsln[l], Wc1[l*64 + j], s);
        h[j] = 0.5f*s*(1.f + erff(s*0.70710678118654752f));
    }
    __syncwarp();

    if (lane < NP) {
        float s = bc2[lane];
#pragma unroll
        for (int j = 0; j < 64; j++) s = fmaf(h[j], Wc2[j*NP + lane], s);
        g_pi[b*NP + lane] = 1.f/(1.f + __expf(-s));
    }

    float g2 = (lane < LATD) ? (d*rs*ln_g_g[lane] + ln_g_b[lane]) * Wg[lane] : 0.f;
    float sg = warp_sum(g2);
    if (lane == 0) g_gw[b] = 1.f/(1.f + __expf(-(sg + bg[0])));

    if (lane < LATD) {
        for (int p = 0; p < NP; p++) {
            float sq = bgq[lane], sl = blq[lane];
#pragma unroll
            for (int l = 0; l < LATD; l++) {
                float pv = pr[p*LATD + l];
                sq = fmaf(pv, Wgq[l*LATD + lane], sq);
                sl = fmaf(pv, Wlq[l*LATD + lane], sl);
            }
            g_qg[(b*NP + p)*LATD + lane] = sq;
            g_ql[(b*NP + p)*LATD + lane] = sl;
        }
    }
}

// ---------------- Kernel 3a: split-softmax attention partials ----------------
__global__ void __launch_bounds__(320, 2)
attn_part_kernel() {
    int blk = blockIdx.x;
    int b = blk / (2*SPLIT);
    int rem = blk % (2*SPLIT);
    int which = rem / SPLIT;
    int sp = rem % SPLIT;
    int tid = threadIdx.x, w = tid >> 5, lane = tid & 31;

    __shared__ __align__(16) float2 ts2[10*CHUNK];
    __shared__ float qs[NP*LATD];

    const float* tok = which
        ? (g_llat + ((size_t)b*NTOK + sp*CHUNK)*LATD)
        : (g_xlat + ((size_t)b*SEQ + NP + 1 + sp*CHUNK)*LATD);
    const float* qsrc = which ? g_ql : g_qg;

#pragma unroll
    for (int it = 0; it < (CHUNK*5)/320; it++) {
        int j = tid + it*320;
        int i = j / 5, c = j % 5;
        float4 x4 = ((const float4*)tok)[j];
        ts2[(2*c    )*CHUNK + i] = make_float2(x4.x, x4.y);
        ts2[(2*c + 1)*CHUNK + i] = make_float2(x4.z, x4.w);
    }
    for (int i = tid; i < NP*LATD; i += 320)
        qs[i] = qsrc[(size_t)b*NP*LATD + i];
    __syncthreads();

    const float scale = 0.22360679774997896f;
    ull q2[10];
#pragma unroll
    for (int p = 0; p < 10; p++) {
        float2 qq = make_float2(qs[w*LATD + 2*p], qs[w*LATD + 2*p + 1]);
        q2[p] = *(ull*)&qq;
    }

    const int TPL = CHUNK/32;
    float sc[TPL];
    float m = -1e30f;
#pragma unroll
    for (int t = 0; t < TPL; t++) {
        int idx = t*32 + lane;
        ull s2 = 0ull;
#pragma unroll
        for (int p = 0; p < 10; p++)
            s2 = fma2(*(const ull*)&ts2[p*CHUNK + idx], q2[p], s2);
        sc[t] = (lo2(s2) + hi2(s2)) * scale;
        m = fmaxf(m, sc[t]);
    }
    m = warp_max(m);

    float sum = 0.f;
    ull acc2[10];
#pragma unroll
    for (int p = 0; p < 10; p++) acc2[p] = 0ull;
#pragma unroll
    for (int t = 0; t < TPL; t++) {
        int idx = t*32 + lane;
        float e = __expf(sc[t] - m);
        sum += e;
        ull e2 = dup2(e);
#pragma unroll
        for (int p = 0; p < 10; p++)
            acc2[p] = fma2(e2, *(const ull*)&ts2[p*CHUNK + idx], acc2[p]);
    }
    sum = warp_sum(sum);
    float acc[LATD];
#pragma unroll
    for (int p = 0; p < 10; p++) { acc[2*p] = lo2(acc2[p]); acc[2*p+1] = hi2(acc2[p]); }
#pragma unroll
    for (int l = 0; l < LATD; l++) acc[l] = warp_sum(acc[l]);

    if (lane == 0) {
        float* dst = g_part + ((((size_t)(b*2 + which)*NP + w)*SPLIT + sp)*22);
        dst[0] = m;
        dst[1] = sum;
#pragma unroll
        for (int l = 0; l < LATD; l++) dst[2 + l] = acc[l];
    }
}

// ---------------- Kernel 3b: combine partials + fuse + enhance ----------------
__global__ void __launch_bounds__(32)
attn_combine_kernel() {
    int b = blockIdx.x / NP, p = blockIdx.x % NP;
    int lane = threadIdx.x;
    float ctxv[2];

#pragma unroll
    for (int which = 0; which < 2; which++) {
        const float* base = g_part + (((size_t)(b*2 + which)*NP + p)*SPLIT)*22;
        float mloc = (lane < SPLIT) ? base[lane*22] : -1e30f;
        float M = warp_max(mloc);
        float wfac = (lane < SPLIT) ? __expf(base[lane*22] - M) : 0.f;
        float S = warp_sum((lane < SPLIT) ? wfac * base[lane*22 + 1] : 0.f);
        float a = 0.f;
#pragma unroll
        for (int s = 0; s < SPLIT; s++) {
            float ws = __shfl_sync(0xffffffffu, wfac, s);
            if (lane < LATD) a = fmaf(base[s*22 + 2 + lane], ws, a);
        }
        ctxv[which] = a / S;
    }
    if (lane < LATD) {
        float g = g_gw[b], im = g_pi[b*NP + p];
        g_xlat[((size_t)b*SEQ + p)*LATD + lane] = im * (g*ctxv[0] + (1.f - g)*ctxv[1]);
    }
}

// ---------------- Kernel 4: out = combined @ Wu + bu ----------------
__global__ void __launch_bounds__(192)
out_kernel(const float* __restrict__ Wu,
           const float* __restrict__ bu,
           float* __restrict__ out) {
    __shared__ __align__(16) float ls[32*LATD];
    int tid = threadIdx.x;
    int c0 = tid*4;

    ull wu2[10][4];
#pragma unroll
    for (int j = 0; j < 10; j++)
#pragma unroll
        for (int c = 0; c < 4; c++) {
            float2 pr = make_float2(Wu[(2*j    )*DIMD + c0 + c],
                                    Wu[(2*j + 1)*DIMD + c0 + c]);
            wu2[j][c] = *(ull*)&pr;
        }
    float bu4[4];
#pragma unroll
    for (int c = 0; c < 4; c++) bu4[c] = bu[c0 + c];

    int nTiles = (NROWS_X + 31) / 32;
    for (int t = blockIdx.x; t < nTiles; t += gridDim.x) {
        int rowBase = t * 32;
        int rmax = min(32, NROWS_X - rowBase);
        __syncthreads();
        for (int i = tid; i < rmax*LATD; i += 192)
            ls[i] = g_xlat[(size_t)rowBase*LATD + i];
        __syncthreads();
        for (int r = 0; r < rmax; r++) {
            const ulonglong2* lr = (const ulonglong2*)(ls + r*LATD);
            ull a0 = 0ull, a1 = 0ull, a2 = 0ull, a3 = 0ull;
#pragma unroll
            for (int j2 = 0; j2 < 5; j2++) {
                ulonglong2 lv = lr[j2];
                a0 = fma2(lv.x, wu2[2*j2][0], a0);
                a1 = fma2(lv.x, wu2[2*j2][1], a1);
                a2 = fma2(lv.x, wu2[2*j2][2], a2);
                a3 = fma2(lv.x, wu2[2*j2][3], a3);
                a0 = fma2(lv.y, wu2[2*j2+1][0], a0);
                a1 = fma2(lv.y, wu2[2*j2+1][1], a1);
                a2 = fma2(lv.y, wu2[2*j2+1][2], a2);
                a3 = fma2(lv.y, wu2[2*j2+1][3], a3);
            }
            float4 o;
            o.x = lo2(a0) + hi2(a0) + bu4[0];
            o.y = lo2(a1) + hi2(a1) + bu4[1];
            o.z = lo2(a2) + hi2(a2) + bu4[2];
            o.w = lo2(a3) + hi2(a3) + bu4[3];
            *(float4*)(out + (size_t)(rowBase + r)*DIMD + c0) = o;
        }
    }
}

// ---------------- launch ----------------
extern "C" void kernel_launch(void* const* d_in, const int* in_sizes, int n_in,
                              void* d_out, int out_size) {
    const float* x      = (const float*)d_in[0];
    const float* loc    = (const float*)d_in[1];
    const float* Wd     = (const float*)d_in[2];
    const float* bd     = (const float*)d_in[3];
    const float* Wu     = (const float*)d_in[4];
    const float* bu     = (const float*)d_in[5];
    const float* Wgq    = (const float*)d_in[6];
    const float* bgq    = (const float*)d_in[7];
    const float* Wlq    = (const float*)d_in[8];
    const float* blq    = (const float*)d_in[9];
    const float* ln_c_g = (const float*)d_in[10];
    const float* ln_c_b = (const float*)d_in[11];
    const float* Wc1    = (const float*)d_in[12];
    const float* bc1    = (const float*)d_in[13];
    const float* Wc2    = (const float*)d_in[14];
    const float* bc2    = (const float*)d_in[15];
    const float* ln_g_g = (const float*)d_in[16];
    const float* ln_g_b = (const float*)d_in[17];
    const float* Wg     = (const float*)d_in[18];
    const float* bg     = (const float*)d_in[19];
    float* out = (float*)d_out;

    cudaFuncSetAttribute(latent_mma_kernel, cudaFuncAttributeMaxDynamicSharedMemorySize, SMEM_MMA_TOTAL);

    latent_mma_kernel<<<NTX + NTL, 256, SMEM_MMA_TOTAL>>>(x, loc, Wd, bd);
    head_kernel<<<BB, 32>>>(ln_c_g, ln_c_b, Wc1, bc1, Wc2, bc2,
                            ln_g_g, ln_g_b, Wg, bg, Wgq, bgq, Wlq, blq);
    attn_part_kernel<<<BB*2*SPLIT, 320>>>();
    attn_combine_kernel<<<BB*NP, 32>>>();
    out_kernel<<<444, 192>>>(Wu, bu, out);
}